// round 8
// baseline (speedup 1.0000x reference)
#include <cuda_runtime.h>
#include <cuda_bf16.h>
#include <cuda_fp16.h>
#include <math.h>

#define NTOK 4096
#define NH   16
#define HD   72
#define HID  1152
#define PROJ 1152

// Scratch (allowed: __device__ globals, no runtime allocation)
__device__ float    g_q [NTOK * PROJ];    // raw QKV gemm outputs (pre-norm)
__device__ float    g_k [NTOK * PROJ];
__device__ float    g_v [NTOK * PROJ];    // raw V, then normalized V (in place)
__device__ unsigned g_qp[NTOK * PROJ];    // packed (bf16 hi, bf16 lo) post norm/rope
__device__ unsigned g_kp[NTOK * PROJ];
__device__ __half   g_vt[NH * 80 * NTOK]; // V transposed [h][dim(80)][token], fp16
__device__ unsigned g_aop[NTOK * PROJ];   // packed attention output
__device__ unsigned g_xp[NTOK * HID];     // packed hidden_states
__device__ unsigned g_wq[HID * PROJ];     // packed weights [k][n]
__device__ unsigned g_wk[HID * PROJ];
__device__ unsigned g_wv[HID * PROJ];
__device__ unsigned g_wo[PROJ * HID];

// ---------------------------------------------------------------------------
// helpers
// ---------------------------------------------------------------------------
__device__ __forceinline__ unsigned pack2(float x) {
    unsigned short hb = __bfloat16_as_ushort(__float2bfloat16_rn(x));
    float hf = __uint_as_float(((unsigned)hb) << 16);
    unsigned short lb = __bfloat16_as_ushort(__float2bfloat16_rn(x - hf));
    return (((unsigned)lb) << 16) | (unsigned)hb;
}

__device__ __forceinline__ void mma_bf16(float d[4], const unsigned a[4],
                                         unsigned b0, unsigned b1) {
    asm volatile(
        "mma.sync.aligned.m16n8k16.row.col.f32.bf16.bf16.f32 "
        "{%0,%1,%2,%3}, {%4,%5,%6,%7}, {%8,%9}, {%0,%1,%2,%3};\n"
        : "+f"(d[0]), "+f"(d[1]), "+f"(d[2]), "+f"(d[3])
        : "r"(a[0]), "r"(a[1]), "r"(a[2]), "r"(a[3]), "r"(b0), "r"(b1));
}

__device__ __forceinline__ void mma_fp16(float d[4], const unsigned a[4],
                                         unsigned b0, unsigned b1) {
    asm volatile(
        "mma.sync.aligned.m16n8k16.row.col.f32.f16.f16.f32 "
        "{%0,%1,%2,%3}, {%4,%5,%6,%7}, {%8,%9}, {%0,%1,%2,%3};\n"
        : "+f"(d[0]), "+f"(d[1]), "+f"(d[2]), "+f"(d[3])
        : "r"(a[0]), "r"(a[1]), "r"(a[2]), "r"(a[3]), "r"(b0), "r"(b1));
}

__device__ __forceinline__ void swap_frag(unsigned s[4], const unsigned a[4]) {
#pragma unroll
    for (int i = 0; i < 4; ++i) s[i] = __byte_perm(a[i], a[i], 0x1032);
}

#define BAR_PAIR(id) asm volatile("bar.sync %0, 64;" :: "r"(id) : "memory")

__global__ __launch_bounds__(256) void pack_kernel(const float* __restrict__ src,
                                                   unsigned* __restrict__ dst, int n4) {
    int i = blockIdx.x * 256 + threadIdx.x;
    if (i < n4) {
        float4 v = ((const float4*)src)[i];
        uint4 o;
        o.x = pack2(v.x); o.y = pack2(v.y); o.z = pack2(v.z); o.w = pack2(v.w);
        ((uint4*)dst)[i] = o;
    }
}

// ---------------------------------------------------------------------------
// Packed bf16 dual-mma GEMM: C[4096,1152] = A @ B, tile 128x128, BK=16 real k.
// 256 threads (8 warps, 2x4), warp tile 64x32, register-prefetched stages.
// Dual 4-term product: pass1 mma(ai), in-place PRMT swap, pass2 mma(swapped).
// ---------------------------------------------------------------------------
#define GAST 20
#define GBST 136

__device__ __forceinline__ void gemm5_body(const unsigned* __restrict__ A,
                                           const unsigned* __restrict__ Bm,
                                           float* __restrict__ C) {
    __shared__ unsigned As[128 * GAST];
    __shared__ unsigned Bs[16 * GBST];

    const int tid  = threadIdx.x;
    const int lane = tid & 31;
    const int wid  = tid >> 5;
    const int wm = wid >> 2, wn = wid & 3;       // 2 x 4 warp grid
    const int qr = lane >> 2, qc = lane & 3;

    const int m0 = blockIdx.y * 128;
    const int n0 = blockIdx.x * 128;

    // load index precompute (2 uint4 per thread for A and B each)
    int arow[2], ac[2], bkr[2], bc[2];
#pragma unroll
    for (int i = 0; i < 2; ++i) {
        int u = tid * 2 + i;
        arow[i] = u >> 2;  ac[i] = (u & 3) * 4;
        bkr[i]  = u >> 5;  bc[i] = (u & 31) * 4;
    }

    float acc[4][4][4] = {};
    uint4 pa[2], pb[2];

#define GLOAD(s) do {                                                        \
    _Pragma("unroll")                                                        \
    for (int i = 0; i < 2; ++i) {                                            \
        pa[i] = *(const uint4*)(A  + (long)(m0 + arow[i]) * 1152 + (s) * 16 + ac[i]); \
        pb[i] = *(const uint4*)(Bm + (long)((s) * 16 + bkr[i]) * 1152 + n0 + bc[i]);  \
    }                                                                        \
} while (0)

    GLOAD(0);

    for (int s = 0; s < 72; ++s) {
        __syncthreads();
#pragma unroll
        for (int i = 0; i < 2; ++i) {
            *(uint4*)(As + arow[i] * GAST + ac[i]) = pa[i];
            *(uint4*)(Bs + bkr[i] * GBST + bc[i]) = pb[i];
        }
        __syncthreads();
        if (s + 1 < 72) GLOAD(s + 1);

#pragma unroll
        for (int ks = 0; ks < 2; ++ks) {
            const int kk = ks * 8;
            unsigned ai[4][4];
#pragma unroll
            for (int mt = 0; mt < 4; ++mt) {
                const unsigned* ap = As + (wm * 64 + mt * 16 + qr) * GAST + kk + qc;
                ai[mt][0] = ap[0];
                ai[mt][1] = ap[8 * GAST];
                ai[mt][2] = ap[4];
                ai[mt][3] = ap[8 * GAST + 4];
            }
            // pass 1: hi*hi + lo*lo
#pragma unroll
            for (int nt = 0; nt < 4; ++nt) {
                const unsigned* bp = Bs + (kk + qc) * GBST + wn * 32 + nt * 8 + qr;
                unsigned b0 = bp[0];
                unsigned b1 = bp[4 * GBST];
#pragma unroll
                for (int mt = 0; mt < 4; ++mt)
                    mma_bf16(acc[mt][nt], ai[mt], b0, b1);
            }
            // swap halves in place, pass 2: lo*hi + hi*lo
#pragma unroll
            for (int mt = 0; mt < 4; ++mt)
#pragma unroll
                for (int j = 0; j < 4; ++j)
                    ai[mt][j] = __byte_perm(ai[mt][j], ai[mt][j], 0x1032);
#pragma unroll
            for (int nt = 0; nt < 4; ++nt) {
                const unsigned* bp = Bs + (kk + qc) * GBST + wn * 32 + nt * 8 + qr;
                unsigned b0 = bp[0];
                unsigned b1 = bp[4 * GBST];
#pragma unroll
                for (int mt = 0; mt < 4; ++mt)
                    mma_bf16(acc[mt][nt], ai[mt], b0, b1);
            }
        }
    }
#undef GLOAD

#pragma unroll
    for (int mt = 0; mt < 4; ++mt) {
        const int row = m0 + wm * 64 + mt * 16 + qr;
#pragma unroll
        for (int nt = 0; nt < 4; ++nt) {
            const int col = n0 + wn * 32 + nt * 8 + qc * 2;
            *(float2*)(C + (long)row * 1152 + col) =
                make_float2(acc[mt][nt][0], acc[mt][nt][1]);
            *(float2*)(C + (long)(row + 8) * 1152 + col) =
                make_float2(acc[mt][nt][2], acc[mt][nt][3]);
        }
    }
}

__global__ __launch_bounds__(256) void gemm_qkv_kernel() {
    const unsigned* B = (blockIdx.z == 0) ? g_wq : (blockIdx.z == 1 ? g_wk : g_wv);
    float* C = (blockIdx.z == 0) ? g_q : (blockIdx.z == 1 ? g_k : g_v);
    gemm5_body(g_xp, B, C);
}

__global__ __launch_bounds__(256) void gemm_out_kernel(float* __restrict__ out) {
    gemm5_body(g_aop, g_wo, out);
}

// ---------------------------------------------------------------------------
// RMSNorm + 2D RoPE; packed q/k, normalized fp32 v in place (coalesced).
// ---------------------------------------------------------------------------
__global__ __launch_bounds__(128) void norm_rope_kernel(const float* __restrict__ cosb,
                                                        const float* __restrict__ sinb,
                                                        const float* __restrict__ qsc,
                                                        const float* __restrict__ ksc) {
    __shared__ float bq[4][HD];
    __shared__ float bk[4][HD];

    const int w = threadIdx.x >> 5;
    const int lane = threadIdx.x & 31;
    const int pair = blockIdx.x * 4 + w;           // = n*16 + h
    const int n = pair >> 4;

    const float* qp = g_q + (long)pair * HD;
    const float* kp = g_k + (long)pair * HD;
    float*       vp = g_v + (long)pair * HD;

    float q0 = qp[lane], q1 = qp[lane + 32], q2 = (lane < 8) ? qp[lane + 64] : 0.0f;
    float k0 = kp[lane], k1 = kp[lane + 32], k2 = (lane < 8) ? kp[lane + 64] : 0.0f;
    float v0 = vp[lane], v1 = vp[lane + 32], v2 = (lane < 8) ? vp[lane + 64] : 0.0f;

    float sq = q0 * q0 + q1 * q1 + q2 * q2;
    float sk = k0 * k0 + k1 * k1 + k2 * k2;
    float sv = v0 * v0 + v1 * v1 + v2 * v2;
#pragma unroll
    for (int o = 16; o > 0; o >>= 1) {
        sq += __shfl_xor_sync(0xffffffffu, sq, o);
        sk += __shfl_xor_sync(0xffffffffu, sk, o);
        sv += __shfl_xor_sync(0xffffffffu, sv, o);
    }
    const float iq = rsqrtf(sq * (1.0f / HD) + 1e-6f);
    const float ik = rsqrtf(sk * (1.0f / HD) + 1e-6f);
    const float iv = rsqrtf(sv * (1.0f / HD) + 1e-6f);

    vp[lane] = v0 * iv;
    vp[lane + 32] = v1 * iv;
    if (lane < 8) vp[lane + 64] = v2 * iv;

    bq[w][lane]      = q0 * iq * qsc[lane];
    bq[w][lane + 32] = q1 * iq * qsc[lane + 32];
    bk[w][lane]      = k0 * ik * ksc[lane];
    bk[w][lane + 32] = k1 * ik * ksc[lane + 32];
    if (lane < 8) {
        bq[w][lane + 64] = q2 * iq * qsc[lane + 64];
        bk[w][lane + 64] = k2 * ik * ksc[lane + 64];
    }
    __syncwarp();

    unsigned* qd = g_qp + (long)pair * HD;
    unsigned* kd = g_kp + (long)pair * HD;
    const float* cr = cosb + (long)n * HD;
    const float* sr = sinb + (long)n * HD;
#pragma unroll
    for (int e = 0; e < 3; ++e) {
        int d = lane + 32 * e;
        if (d < HD) {
            float c = cr[d], s = sr[d];
            int loc = d % 36;
            int prt = (loc < 18) ? d + 18 : d - 18;
            float sgn = (loc < 18) ? -1.0f : 1.0f;
            qd[d] = pack2(bq[w][d] * c + sgn * bq[w][prt] * s);
            kd[d] = pack2(bk[w][d] * c + sgn * bk[w][prt] * s);
        }
    }
}

// ---------------------------------------------------------------------------
// V transpose: g_v fp32 [n][h*72+d] -> g_vt fp16 [h][80][token].
// ---------------------------------------------------------------------------
__global__ __launch_bounds__(256) void vtrans_kernel() {
    __shared__ __half sm[64 * 83];
    const int t0 = blockIdx.x * 64;
    const int h  = blockIdx.y;
    const int tid = threadIdx.x;

    for (int idx = tid; idx < 64 * 72; idx += 256) {
        int r = idx / 72, d = idx - r * 72;
        sm[r * 83 + d] = __float2half_rn(g_v[(long)(t0 + r) * PROJ + h * HD + d]);
    }
    __syncthreads();

    __half2* vt2 = (__half2*)g_vt + ((long)h * 80) * (NTOK / 2) + (t0 >> 1);
    for (int idx = tid; idx < 72 * 32; idx += 256) {
        int d = idx >> 5, c = idx & 31;
        __half2 val;
        val.x = sm[(2 * c) * 83 + d];
        val.y = sm[(2 * c + 1) * 83 + d];
        vt2[(long)d * (NTOK / 2) + c] = val;
    }
}

// ---------------------------------------------------------------------------
// Flash attention: S = QK^T packed-bf16 dual-mma; PV fp16 single-mma.
// Softmax stats in registers; warp-pair named barriers instead of block syncs.
// ---------------------------------------------------------------------------
#define QST  76
#define VTST 36
#define PSTU 36
#define OQ   0
#define OK_  4864
#define OVT  9728
#define OP   12608
#define OTM  14912
#define OTS  15040
#define ASMEM_WORDS 15168

__global__ __launch_bounds__(256) void attn_kernel() {
    extern __shared__ unsigned smu[];
    unsigned* Qs  = smu + OQ;
    unsigned* Ks  = smu + OK_;
    unsigned* VTs = smu + OVT;
    unsigned* Ps  = smu + OP;
    float* tmax = (float*)(smu + OTM);   // [2][64]
    float* tsum = (float*)(smu + OTS);   // [2][64]

    const int h  = blockIdx.y;
    const int q0 = blockIdx.x * 64;
    const int tid  = threadIdx.x;
    const int lane = tid & 31;
    const int wid  = tid >> 5;
    const int mg = wid >> 1;
    const int ng = wid & 1;
    const int qr = lane >> 2, qc = lane & 3;
    const int r0 = mg * 16 + qr;
    const int r1 = r0 + 8;
    const int barid = mg + 1;

    const unsigned* vt_u32 = (const unsigned*)(g_vt) + (long)h * 80 * (NTOK / 2);

    for (int idx = tid; idx < 1152; idx += 256) {
        int r = idx / 18, d4 = (idx - r * 18) * 4;
        uint4 v = *(const uint4*)(g_qp + (long)(q0 + r) * PROJ + h * HD + d4);
        Qs[r * QST + d4 + 0] = v.x; Qs[r * QST + d4 + 1] = v.y;
        Qs[r * QST + d4 + 2] = v.z; Qs[r * QST + d4 + 3] = v.w;
    }

    float acc[5][4] = {};
    float m0r = -1e30f, m1r = -1e30f, l0r = 0.0f, l1r = 0.0f;

    for (int j = 0; j < NTOK / 64; ++j) {
        const int kb = j * 64;
        __syncthreads();   // all pairs done reading prior K/VT

        for (int idx = tid; idx < 1152; idx += 256) {
            int r = idx / 18, d4 = (idx - r * 18) * 4;
            uint4 kv = *(const uint4*)(g_kp + (long)(kb + r) * PROJ + h * HD + d4);
            Ks[r * QST + d4 + 0] = kv.x; Ks[r * QST + d4 + 1] = kv.y;
            Ks[r * QST + d4 + 2] = kv.z; Ks[r * QST + d4 + 3] = kv.w;
        }
        for (int idx = tid; idx < 2560; idx += 256) {
            int r = idx >> 5, c = idx & 31;
            VTs[r * VTST + c] = vt_u32[(long)r * (NTOK / 2) + (kb >> 1) + c];
        }
        __syncthreads();

        // ---- S = Q @ K^T (packed bf16 dual-mma) ----
        float s[4][4] = {};
#pragma unroll
        for (int ks = 0; ks < 9; ++ks) {
            const int kk = ks * 8;
            unsigned ai[4], asw[4];
            const unsigned* ap = Qs + (long)r0 * QST + kk + qc;
            ai[0] = ap[0];
            ai[1] = ap[8 * QST];
            ai[2] = ap[4];
            ai[3] = ap[8 * QST + 4];
            swap_frag(asw, ai);
#pragma unroll
            for (int nt = 0; nt < 4; ++nt) {
                const unsigned* bp = Ks + (ng * 32 + nt * 8 + qr) * QST + kk + qc;
                unsigned b0 = bp[0];
                unsigned b1 = bp[4];
                mma_bf16(s[nt], ai,  b0, b1);
                mma_bf16(s[nt], asw, b0, b1);
            }
        }

        // ---- row max (within warp: qc partners) ----
        float mx0 = -1e30f, mx1 = -1e30f;
#pragma unroll
        for (int nt = 0; nt < 4; ++nt) {
            mx0 = fmaxf(mx0, fmaxf(s[nt][0], s[nt][1]));
            mx1 = fmaxf(mx1, fmaxf(s[nt][2], s[nt][3]));
        }
        mx0 = fmaxf(mx0, __shfl_xor_sync(0xffffffffu, mx0, 1));
        mx0 = fmaxf(mx0, __shfl_xor_sync(0xffffffffu, mx0, 2));
        mx1 = fmaxf(mx1, __shfl_xor_sync(0xffffffffu, mx1, 1));
        mx1 = fmaxf(mx1, __shfl_xor_sync(0xffffffffu, mx1, 2));
        if (qc == 0) { tmax[ng * 64 + r0] = mx0; tmax[ng * 64 + r1] = mx1; }
        BAR_PAIR(barid);

        const float mn0 = fmaxf(m0r, fmaxf(tmax[r0], tmax[64 + r0]));
        const float mn1 = fmaxf(m1r, fmaxf(tmax[r1], tmax[64 + r1]));
        const float sc0 = __expf(m0r - mn0);
        const float sc1 = __expf(m1r - mn1);

        // ---- p = exp(s - m), store fp16 P, partial row sums ----
        float sum0 = 0.0f, sum1 = 0.0f;
#pragma unroll
        for (int nt = 0; nt < 4; ++nt) {
            const int cu = ng * 16 + nt * 4 + qc;
            float p0 = __expf(s[nt][0] - mn0);
            float p1 = __expf(s[nt][1] - mn0);
            float p2 = __expf(s[nt][2] - mn1);
            float p3 = __expf(s[nt][3] - mn1);
            sum0 += p0 + p1;
            sum1 += p2 + p3;
            *(__half2*)(Ps + r0 * PSTU + cu) = __floats2half2_rn(p0, p1);
            *(__half2*)(Ps + r1 * PSTU + cu) = __floats2half2_rn(p2, p3);
        }
        sum0 += __shfl_xor_sync(0xffffffffu, sum0, 1);
        sum0 += __shfl_xor_sync(0xffffffffu, sum0, 2);
        sum1 += __shfl_xor_sync(0xffffffffu, sum1, 1);
        sum1 += __shfl_xor_sync(0xffffffffu, sum1, 2);
        if (qc == 0) { tsum[ng * 64 + r0] = sum0; tsum[ng * 64 + r1] = sum1; }
        BAR_PAIR(barid);

        l0r = l0r * sc0 + tsum[r0] + tsum[64 + r0];
        l1r = l1r * sc1 + tsum[r1] + tsum[64 + r1];
        m0r = mn0; m1r = mn1;
#pragma unroll
        for (int dt = 0; dt < 5; ++dt) {
            acc[dt][0] *= sc0; acc[dt][1] *= sc0;
            acc[dt][2] *= sc1; acc[dt][3] *= sc1;
        }

        // ---- acc += P @ V (fp16 single-mma, 16 real k per mma) ----
#pragma unroll
        for (int ks = 0; ks < 4; ++ks) {
            const int kku = ks * 8;
            unsigned ai[4];
            const unsigned* ap = Ps + (long)r0 * PSTU + kku + qc;
            ai[0] = ap[0];
            ai[1] = ap[8 * PSTU];
            ai[2] = ap[4];
            ai[3] = ap[8 * PSTU + 4];
#pragma unroll
            for (int dt = 0; dt < 5; ++dt) {
                const unsigned* bp = VTs + (ng * 40 + dt * 8 + qr) * VTST + kku + qc;
                unsigned b0 = bp[0];
                unsigned b1 = bp[4];
                mma_fp16(acc[dt], ai, b0, b1);
            }
        }
    }

    const float il0 = 1.0f / l0r;
    const float il1 = 1.0f / l1r;
#pragma unroll
    for (int dt = 0; dt < 5; ++dt) {
        const int d = ng * 40 + dt * 8 + qc * 2;
        if (d < HD) {
            uint2 w0; w0.x = pack2(acc[dt][0] * il0); w0.y = pack2(acc[dt][1] * il0);
            uint2 w1; w1.x = pack2(acc[dt][2] * il1); w1.y = pack2(acc[dt][3] * il1);
            *(uint2*)(g_aop + (long)(q0 + r0) * PROJ + h * HD + d) = w0;
            *(uint2*)(g_aop + (long)(q0 + r1) * PROJ + h * HD + d) = w1;
        }
    }
}

// ---------------------------------------------------------------------------
extern "C" void kernel_launch(void* const* d_in, const int* in_sizes, int n_in,
                              void* d_out, int out_size) {
    const float* X    = (const float*)d_in[0];
    const float* cosb = (const float*)d_in[1];
    const float* sinb = (const float*)d_in[2];
    const float* Wq   = (const float*)d_in[3];
    const float* Wk   = (const float*)d_in[4];
    const float* Wv   = (const float*)d_in[5];
    const float* Wo   = (const float*)d_in[6];
    const float* qsc  = (const float*)d_in[7];
    const float* ksc  = (const float*)d_in[8];
    float* out = (float*)d_out;

    const int asmem = ASMEM_WORDS * (int)sizeof(unsigned);
    cudaFuncSetAttribute(attn_kernel, cudaFuncAttributeMaxDynamicSharedMemorySize, asmem);

    unsigned* xp; cudaGetSymbolAddress((void**)&xp, g_xp);
    unsigned* wq; cudaGetSymbolAddress((void**)&wq, g_wq);
    unsigned* wk; cudaGetSymbolAddress((void**)&wk, g_wk);
    unsigned* wv; cudaGetSymbolAddress((void**)&wv, g_wv);
    unsigned* wo; cudaGetSymbolAddress((void**)&wo, g_wo);

    const int nx4 = NTOK * HID / 4;
    const int nw4 = HID * PROJ / 4;
    pack_kernel<<<(nx4 + 255) / 256, 256>>>(X,  xp, nx4);
    pack_kernel<<<(nw4 + 255) / 256, 256>>>(Wq, wq, nw4);
    pack_kernel<<<(nw4 + 255) / 256, 256>>>(Wk, wk, nw4);
    pack_kernel<<<(nw4 + 255) / 256, 256>>>(Wv, wv, nw4);
    pack_kernel<<<(nw4 + 255) / 256, 256>>>(Wo, wo, nw4);

    gemm_qkv_kernel<<<dim3(PROJ / 128, NTOK / 128, 3), 256>>>();
    norm_rope_kernel<<<(NTOK * NH) / 4, 128>>>(cosb, sinb, qsc, ksc);
    vtrans_kernel<<<dim3(NTOK / 64, NH), 256>>>();
    attn_kernel<<<dim3(NTOK / 64, NH), 256, asmem>>>();
    gemm_out_kernel<<<dim3(HID / 128, NTOK / 128), 256>>>(out);
}

// round 9
// speedup vs baseline: 1.0667x; 1.0667x over previous
#include <cuda_runtime.h>
#include <cuda_bf16.h>
#include <cuda_fp16.h>
#include <math.h>

#define NTOK 4096
#define NH   16
#define HD   72
#define HID  1152
#define PROJ 1152

// Scratch (allowed: __device__ globals, no runtime allocation)
__device__ float    g_q [NTOK * PROJ];    // raw QKV gemm outputs (pre-norm)
__device__ float    g_k [NTOK * PROJ];
__device__ float    g_v [NTOK * PROJ];    // raw V, then normalized V (in place)
__device__ unsigned g_qp[NTOK * PROJ];    // packed (bf16 hi, bf16 lo) post norm/rope
__device__ unsigned g_kp[NTOK * PROJ];
__device__ __half   g_vt[NH * 80 * NTOK]; // V transposed [h][dim(80)][token], fp16
__device__ unsigned g_aop[NTOK * PROJ];   // packed attention output
__device__ unsigned g_xp[NTOK * HID];     // packed hidden_states
__device__ unsigned g_wq[HID * PROJ];     // packed weights [k][n]
__device__ unsigned g_wk[HID * PROJ];
__device__ unsigned g_wv[HID * PROJ];
__device__ unsigned g_wo[PROJ * HID];

// ---------------------------------------------------------------------------
// helpers
// ---------------------------------------------------------------------------
__device__ __forceinline__ unsigned pack2(float x) {
    unsigned short hb = __bfloat16_as_ushort(__float2bfloat16_rn(x));
    float hf = __uint_as_float(((unsigned)hb) << 16);
    unsigned short lb = __bfloat16_as_ushort(__float2bfloat16_rn(x - hf));
    return (((unsigned)lb) << 16) | (unsigned)hb;
}

__device__ __forceinline__ void mma_bf16(float d[4], const unsigned a[4],
                                         unsigned b0, unsigned b1) {
    asm volatile(
        "mma.sync.aligned.m16n8k16.row.col.f32.bf16.bf16.f32 "
        "{%0,%1,%2,%3}, {%4,%5,%6,%7}, {%8,%9}, {%0,%1,%2,%3};\n"
        : "+f"(d[0]), "+f"(d[1]), "+f"(d[2]), "+f"(d[3])
        : "r"(a[0]), "r"(a[1]), "r"(a[2]), "r"(a[3]), "r"(b0), "r"(b1));
}

__device__ __forceinline__ void mma_fp16(float d[4], const unsigned a[4],
                                         unsigned b0, unsigned b1) {
    asm volatile(
        "mma.sync.aligned.m16n8k16.row.col.f32.f16.f16.f32 "
        "{%0,%1,%2,%3}, {%4,%5,%6,%7}, {%8,%9}, {%0,%1,%2,%3};\n"
        : "+f"(d[0]), "+f"(d[1]), "+f"(d[2]), "+f"(d[3])
        : "r"(a[0]), "r"(a[1]), "r"(a[2]), "r"(a[3]), "r"(b0), "r"(b1));
}

__device__ __forceinline__ void swap_frag(unsigned s[4], const unsigned a[4]) {
#pragma unroll
    for (int i = 0; i < 4; ++i) s[i] = __byte_perm(a[i], a[i], 0x1032);
}

#define BAR_PAIR(id) asm volatile("bar.sync %0, 64;" :: "r"(id) : "memory")

__global__ __launch_bounds__(256) void pack_kernel(const float* __restrict__ src,
                                                   unsigned* __restrict__ dst, int n4) {
    int i = blockIdx.x * 256 + threadIdx.x;
    if (i < n4) {
        float4 v = ((const float4*)src)[i];
        uint4 o;
        o.x = pack2(v.x); o.y = pack2(v.y); o.z = pack2(v.z); o.w = pack2(v.w);
        ((uint4*)dst)[i] = o;
    }
}

// ---------------------------------------------------------------------------
// Packed bf16 dual-mma GEMM (R6-proven): C = A @ B, tile 64x128, BK=16 real k.
// 256 threads (8 warps, 2x4), warp tile 32x32.
// ---------------------------------------------------------------------------
#define GAST 20
#define GBST 136

__device__ __forceinline__ void gemm4_body(const unsigned* __restrict__ A,
                                           const unsigned* __restrict__ Bm,
                                           float* __restrict__ C) {
    __shared__ unsigned As[64 * GAST];
    __shared__ unsigned Bs[16 * GBST];

    const int tid  = threadIdx.x;
    const int lane = tid & 31;
    const int wid  = tid >> 5;
    const int wm = wid >> 2, wn = wid & 3;
    const int qr = lane >> 2, qc = lane & 3;

    const int m0 = blockIdx.y * 64;
    const int n0 = blockIdx.x * 128;

    const int ar = tid >> 2;
    const int ac = (tid & 3) * 4;
    const int br = tid >> 5;
    const int bc = (tid & 31) * 4;

    float acc[2][4][4] = {};

    for (int k0 = 0; k0 < 1152; k0 += 16) {
        uint4 av  = *(const uint4*)(A  + (long)(m0 + ar) * 1152 + k0 + ac);
        uint4 bv0 = *(const uint4*)(Bm + (long)(k0 + br) * 1152 + n0 + bc);
        uint4 bv1 = *(const uint4*)(Bm + (long)(k0 + br + 8) * 1152 + n0 + bc);

        __syncthreads();
        As[ar * GAST + ac + 0] = av.x;
        As[ar * GAST + ac + 1] = av.y;
        As[ar * GAST + ac + 2] = av.z;
        As[ar * GAST + ac + 3] = av.w;
        Bs[br * GBST + bc + 0] = bv0.x;
        Bs[br * GBST + bc + 1] = bv0.y;
        Bs[br * GBST + bc + 2] = bv0.z;
        Bs[br * GBST + bc + 3] = bv0.w;
        Bs[(br + 8) * GBST + bc + 0] = bv1.x;
        Bs[(br + 8) * GBST + bc + 1] = bv1.y;
        Bs[(br + 8) * GBST + bc + 2] = bv1.z;
        Bs[(br + 8) * GBST + bc + 3] = bv1.w;
        __syncthreads();

#pragma unroll
        for (int ks = 0; ks < 2; ++ks) {
            const int kk = ks * 8;
            unsigned ai[2][4], asw[2][4];
#pragma unroll
            for (int mt = 0; mt < 2; ++mt) {
                const unsigned* ap = As + (wm * 32 + mt * 16 + qr) * GAST + kk + qc;
                ai[mt][0] = ap[0];
                ai[mt][1] = ap[8 * GAST];
                ai[mt][2] = ap[4];
                ai[mt][3] = ap[8 * GAST + 4];
                swap_frag(asw[mt], ai[mt]);
            }
#pragma unroll
            for (int nt = 0; nt < 4; ++nt) {
                const unsigned* bp = Bs + (kk + qc) * GBST + wn * 32 + nt * 8 + qr;
                unsigned b0 = bp[0];
                unsigned b1 = bp[4 * GBST];
#pragma unroll
                for (int mt = 0; mt < 2; ++mt) {
                    mma_bf16(acc[mt][nt], ai[mt],  b0, b1);
                    mma_bf16(acc[mt][nt], asw[mt], b0, b1);
                }
            }
        }
    }

#pragma unroll
    for (int mt = 0; mt < 2; ++mt) {
        const int row = m0 + wm * 32 + mt * 16 + qr;
#pragma unroll
        for (int nt = 0; nt < 4; ++nt) {
            const int col = n0 + wn * 32 + nt * 8 + qc * 2;
            *(float2*)(C + (long)row * 1152 + col) =
                make_float2(acc[mt][nt][0], acc[mt][nt][1]);
            *(float2*)(C + (long)(row + 8) * 1152 + col) =
                make_float2(acc[mt][nt][2], acc[mt][nt][3]);
        }
    }
}

__global__ __launch_bounds__(256) void gemm_qkv_kernel() {
    const unsigned* B = (blockIdx.z == 0) ? g_wq : (blockIdx.z == 1 ? g_wk : g_wv);
    float* C = (blockIdx.z == 0) ? g_q : (blockIdx.z == 1 ? g_k : g_v);
    gemm4_body(g_xp, B, C);
}

__global__ __launch_bounds__(256) void gemm_out_kernel(float* __restrict__ out) {
    gemm4_body(g_aop, g_wo, out);
}

// ---------------------------------------------------------------------------
// RMSNorm + 2D RoPE; packed q/k, normalized fp32 v in place (coalesced).
// ---------------------------------------------------------------------------
__global__ __launch_bounds__(128) void norm_rope_kernel(const float* __restrict__ cosb,
                                                        const float* __restrict__ sinb,
                                                        const float* __restrict__ qsc,
                                                        const float* __restrict__ ksc) {
    __shared__ float bq[4][HD];
    __shared__ float bk[4][HD];

    const int w = threadIdx.x >> 5;
    const int lane = threadIdx.x & 31;
    const int pair = blockIdx.x * 4 + w;           // = n*16 + h
    const int n = pair >> 4;

    const float* qp = g_q + (long)pair * HD;
    const float* kp = g_k + (long)pair * HD;
    float*       vp = g_v + (long)pair * HD;

    float q0 = qp[lane], q1 = qp[lane + 32], q2 = (lane < 8) ? qp[lane + 64] : 0.0f;
    float k0 = kp[lane], k1 = kp[lane + 32], k2 = (lane < 8) ? kp[lane + 64] : 0.0f;
    float v0 = vp[lane], v1 = vp[lane + 32], v2 = (lane < 8) ? vp[lane + 64] : 0.0f;

    float sq = q0 * q0 + q1 * q1 + q2 * q2;
    float sk = k0 * k0 + k1 * k1 + k2 * k2;
    float sv = v0 * v0 + v1 * v1 + v2 * v2;
#pragma unroll
    for (int o = 16; o > 0; o >>= 1) {
        sq += __shfl_xor_sync(0xffffffffu, sq, o);
        sk += __shfl_xor_sync(0xffffffffu, sk, o);
        sv += __shfl_xor_sync(0xffffffffu, sv, o);
    }
    const float iq = rsqrtf(sq * (1.0f / HD) + 1e-6f);
    const float ik = rsqrtf(sk * (1.0f / HD) + 1e-6f);
    const float iv = rsqrtf(sv * (1.0f / HD) + 1e-6f);

    vp[lane] = v0 * iv;
    vp[lane + 32] = v1 * iv;
    if (lane < 8) vp[lane + 64] = v2 * iv;

    bq[w][lane]      = q0 * iq * qsc[lane];
    bq[w][lane + 32] = q1 * iq * qsc[lane + 32];
    bk[w][lane]      = k0 * ik * ksc[lane];
    bk[w][lane + 32] = k1 * ik * ksc[lane + 32];
    if (lane < 8) {
        bq[w][lane + 64] = q2 * iq * qsc[lane + 64];
        bk[w][lane + 64] = k2 * ik * ksc[lane + 64];
    }
    __syncwarp();

    unsigned* qd = g_qp + (long)pair * HD;
    unsigned* kd = g_kp + (long)pair * HD;
    const float* cr = cosb + (long)n * HD;
    const float* sr = sinb + (long)n * HD;
#pragma unroll
    for (int e = 0; e < 3; ++e) {
        int d = lane + 32 * e;
        if (d < HD) {
            float c = cr[d], s = sr[d];
            int loc = d % 36;
            int prt = (loc < 18) ? d + 18 : d - 18;
            float sgn = (loc < 18) ? -1.0f : 1.0f;
            qd[d] = pack2(bq[w][d] * c + sgn * bq[w][prt] * s);
            kd[d] = pack2(bk[w][d] * c + sgn * bk[w][prt] * s);
        }
    }
}

// ---------------------------------------------------------------------------
// V transpose: g_v fp32 [n][h*72+d] -> g_vt fp16 [h][80][token].
// ---------------------------------------------------------------------------
__global__ __launch_bounds__(256) void vtrans_kernel() {
    __shared__ __half sm[64 * 83];
    const int t0 = blockIdx.x * 64;
    const int h  = blockIdx.y;
    const int tid = threadIdx.x;

    for (int idx = tid; idx < 64 * 72; idx += 256) {
        int r = idx / 72, d = idx - r * 72;
        sm[r * 83 + d] = __float2half_rn(g_v[(long)(t0 + r) * PROJ + h * HD + d]);
    }
    __syncthreads();

    __half2* vt2 = (__half2*)g_vt + ((long)h * 80) * (NTOK / 2) + (t0 >> 1);
    for (int idx = tid; idx < 72 * 32; idx += 256) {
        int d = idx >> 5, c = idx & 31;
        __half2 val;
        val.x = sm[(2 * c) * 83 + d];
        val.y = sm[(2 * c + 1) * 83 + d];
        vt2[(long)d * (NTOK / 2) + c] = val;
    }
}

// ---------------------------------------------------------------------------
// Flash attention: S = QK^T packed-bf16 dual-mma; PV fp16 single-mma.
// Softmax stats in registers; warp-pair named barriers instead of block syncs.
// ---------------------------------------------------------------------------
#define QST  76
#define VTST 36
#define PSTU 36
#define OQ   0
#define OK_  4864
#define OVT  9728
#define OP   12608
#define OTM  14912
#define OTS  15040
#define ASMEM_WORDS 15168

__global__ __launch_bounds__(256) void attn_kernel() {
    extern __shared__ unsigned smu[];
    unsigned* Qs  = smu + OQ;
    unsigned* Ks  = smu + OK_;
    unsigned* VTs = smu + OVT;
    unsigned* Ps  = smu + OP;
    float* tmax = (float*)(smu + OTM);   // [2][64]
    float* tsum = (float*)(smu + OTS);   // [2][64]

    const int h  = blockIdx.y;
    const int q0 = blockIdx.x * 64;
    const int tid  = threadIdx.x;
    const int lane = tid & 31;
    const int wid  = tid >> 5;
    const int mg = wid >> 1;
    const int ng = wid & 1;
    const int qr = lane >> 2, qc = lane & 3;
    const int r0 = mg * 16 + qr;
    const int r1 = r0 + 8;
    const int barid = mg + 1;

    const unsigned* vt_u32 = (const unsigned*)(g_vt) + (long)h * 80 * (NTOK / 2);

    for (int idx = tid; idx < 1152; idx += 256) {
        int r = idx / 18, d4 = (idx - r * 18) * 4;
        uint4 v = *(const uint4*)(g_qp + (long)(q0 + r) * PROJ + h * HD + d4);
        Qs[r * QST + d4 + 0] = v.x; Qs[r * QST + d4 + 1] = v.y;
        Qs[r * QST + d4 + 2] = v.z; Qs[r * QST + d4 + 3] = v.w;
    }

    float acc[5][4] = {};
    float m0r = -1e30f, m1r = -1e30f, l0r = 0.0f, l1r = 0.0f;

    for (int j = 0; j < NTOK / 64; ++j) {
        const int kb = j * 64;
        __syncthreads();   // all pairs done reading prior K/VT

        for (int idx = tid; idx < 1152; idx += 256) {
            int r = idx / 18, d4 = (idx - r * 18) * 4;
            uint4 kv = *(const uint4*)(g_kp + (long)(kb + r) * PROJ + h * HD + d4);
            Ks[r * QST + d4 + 0] = kv.x; Ks[r * QST + d4 + 1] = kv.y;
            Ks[r * QST + d4 + 2] = kv.z; Ks[r * QST + d4 + 3] = kv.w;
        }
        for (int idx = tid; idx < 2560; idx += 256) {
            int r = idx >> 5, c = idx & 31;
            VTs[r * VTST + c] = vt_u32[(long)r * (NTOK / 2) + (kb >> 1) + c];
        }
        __syncthreads();

        // ---- S = Q @ K^T (packed bf16 dual-mma) ----
        float s[4][4] = {};
#pragma unroll
        for (int ks = 0; ks < 9; ++ks) {
            const int kk = ks * 8;
            unsigned ai[4], asw[4];
            const unsigned* ap = Qs + (long)r0 * QST + kk + qc;
            ai[0] = ap[0];
            ai[1] = ap[8 * QST];
            ai[2] = ap[4];
            ai[3] = ap[8 * QST + 4];
            swap_frag(asw, ai);
#pragma unroll
            for (int nt = 0; nt < 4; ++nt) {
                const unsigned* bp = Ks + (ng * 32 + nt * 8 + qr) * QST + kk + qc;
                unsigned b0 = bp[0];
                unsigned b1 = bp[4];
                mma_bf16(s[nt], ai,  b0, b1);
                mma_bf16(s[nt], asw, b0, b1);
            }
        }

        // ---- row max (within warp: qc partners) ----
        float mx0 = -1e30f, mx1 = -1e30f;
#pragma unroll
        for (int nt = 0; nt < 4; ++nt) {
            mx0 = fmaxf(mx0, fmaxf(s[nt][0], s[nt][1]));
            mx1 = fmaxf(mx1, fmaxf(s[nt][2], s[nt][3]));
        }
        mx0 = fmaxf(mx0, __shfl_xor_sync(0xffffffffu, mx0, 1));
        mx0 = fmaxf(mx0, __shfl_xor_sync(0xffffffffu, mx0, 2));
        mx1 = fmaxf(mx1, __shfl_xor_sync(0xffffffffu, mx1, 1));
        mx1 = fmaxf(mx1, __shfl_xor_sync(0xffffffffu, mx1, 2));
        if (qc == 0) { tmax[ng * 64 + r0] = mx0; tmax[ng * 64 + r1] = mx1; }
        BAR_PAIR(barid);

        const float mn0 = fmaxf(m0r, fmaxf(tmax[r0], tmax[64 + r0]));
        const float mn1 = fmaxf(m1r, fmaxf(tmax[r1], tmax[64 + r1]));
        const float sc0 = __expf(m0r - mn0);
        const float sc1 = __expf(m1r - mn1);

        // ---- p = exp(s - m), store fp16 P, partial row sums ----
        float sum0 = 0.0f, sum1 = 0.0f;
#pragma unroll
        for (int nt = 0; nt < 4; ++nt) {
            const int cu = ng * 16 + nt * 4 + qc;
            float p0 = __expf(s[nt][0] - mn0);
            float p1 = __expf(s[nt][1] - mn0);
            float p2 = __expf(s[nt][2] - mn1);
            float p3 = __expf(s[nt][3] - mn1);
            sum0 += p0 + p1;
            sum1 += p2 + p3;
            *(__half2*)(Ps + r0 * PSTU + cu) = __floats2half2_rn(p0, p1);
            *(__half2*)(Ps + r1 * PSTU + cu) = __floats2half2_rn(p2, p3);
        }
        sum0 += __shfl_xor_sync(0xffffffffu, sum0, 1);
        sum0 += __shfl_xor_sync(0xffffffffu, sum0, 2);
        sum1 += __shfl_xor_sync(0xffffffffu, sum1, 1);
        sum1 += __shfl_xor_sync(0xffffffffu, sum1, 2);
        if (qc == 0) { tsum[ng * 64 + r0] = sum0; tsum[ng * 64 + r1] = sum1; }
        BAR_PAIR(barid);

        l0r = l0r * sc0 + tsum[r0] + tsum[64 + r0];
        l1r = l1r * sc1 + tsum[r1] + tsum[64 + r1];
        m0r = mn0; m1r = mn1;
#pragma unroll
        for (int dt = 0; dt < 5; ++dt) {
            acc[dt][0] *= sc0; acc[dt][1] *= sc0;
            acc[dt][2] *= sc1; acc[dt][3] *= sc1;
        }

        // ---- acc += P @ V (fp16 single-mma, 16 real k per mma) ----
#pragma unroll
        for (int ks = 0; ks < 4; ++ks) {
            const int kku = ks * 8;
            unsigned ai[4];
            const unsigned* ap = Ps + (long)r0 * PSTU + kku + qc;
            ai[0] = ap[0];
            ai[1] = ap[8 * PSTU];
            ai[2] = ap[4];
            ai[3] = ap[8 * PSTU + 4];
#pragma unroll
            for (int dt = 0; dt < 5; ++dt) {
                const unsigned* bp = VTs + (ng * 40 + dt * 8 + qr) * VTST + kku + qc;
                unsigned b0 = bp[0];
                unsigned b1 = bp[4];
                mma_fp16(acc[dt], ai, b0, b1);
            }
        }
    }

    const float il0 = 1.0f / l0r;
    const float il1 = 1.0f / l1r;
#pragma unroll
    for (int dt = 0; dt < 5; ++dt) {
        const int d = ng * 40 + dt * 8 + qc * 2;
        if (d < HD) {
            uint2 w0; w0.x = pack2(acc[dt][0] * il0); w0.y = pack2(acc[dt][1] * il0);
            uint2 w1; w1.x = pack2(acc[dt][2] * il1); w1.y = pack2(acc[dt][3] * il1);
            *(uint2*)(g_aop + (long)(q0 + r0) * PROJ + h * HD + d) = w0;
            *(uint2*)(g_aop + (long)(q0 + r1) * PROJ + h * HD + d) = w1;
        }
    }
}

// ---------------------------------------------------------------------------
extern "C" void kernel_launch(void* const* d_in, const int* in_sizes, int n_in,
                              void* d_out, int out_size) {
    const float* X    = (const float*)d_in[0];
    const float* cosb = (const float*)d_in[1];
    const float* sinb = (const float*)d_in[2];
    const float* Wq   = (const float*)d_in[3];
    const float* Wk   = (const float*)d_in[4];
    const float* Wv   = (const float*)d_in[5];
    const float* Wo   = (const float*)d_in[6];
    const float* qsc  = (const float*)d_in[7];
    const float* ksc  = (const float*)d_in[8];
    float* out = (float*)d_out;

    const int asmem = ASMEM_WORDS * (int)sizeof(unsigned);
    cudaFuncSetAttribute(attn_kernel, cudaFuncAttributeMaxDynamicSharedMemorySize, asmem);

    unsigned* xp; cudaGetSymbolAddress((void**)&xp, g_xp);
    unsigned* wq; cudaGetSymbolAddress((void**)&wq, g_wq);
    unsigned* wk; cudaGetSymbolAddress((void**)&wk, g_wk);
    unsigned* wv; cudaGetSymbolAddress((void**)&wv, g_wv);
    unsigned* wo; cudaGetSymbolAddress((void**)&wo, g_wo);

    const int nx4 = NTOK * HID / 4;
    const int nw4 = HID * PROJ / 4;
    pack_kernel<<<(nx4 + 255) / 256, 256>>>(X,  xp, nx4);
    pack_kernel<<<(nw4 + 255) / 256, 256>>>(Wq, wq, nw4);
    pack_kernel<<<(nw4 + 255) / 256, 256>>>(Wk, wk, nw4);
    pack_kernel<<<(nw4 + 255) / 256, 256>>>(Wv, wv, nw4);
    pack_kernel<<<(nw4 + 255) / 256, 256>>>(Wo, wo, nw4);

    gemm_qkv_kernel<<<dim3(PROJ / 128, NTOK / 64, 3), 256>>>();
    norm_rope_kernel<<<(NTOK * NH) / 4, 128>>>(cosb, sinb, qsc, ksc);
    vtrans_kernel<<<dim3(NTOK / 64, NH), 256>>>();
    attn_kernel<<<dim3(NTOK / 64, NH), 256, asmem>>>();
    gemm_out_kernel<<<dim3(HID / 128, NTOK / 64), 256>>>(out);
}